// round 9
// baseline (speedup 1.0000x reference)
#include <cuda_runtime.h>
#include <mma.h>
#include <cstdint>
#include <cstddef>

using namespace nvcuda;

// Problem constants
#define Bc   256
#define HIDc 512
#define Hc   8
#define Dc   64
#define FFc  2048
#define Lc   6

#define EPS_ATTN 1e-6f
#define EPS_LN   1e-5f

#define MNc (Bc * HIDc)   // 131072

// ---------------- scratch (device globals; no allocations allowed) ----------
__device__ float g_h[MNc];
__device__ float g_attn[MNc];
__device__ float g_ff[Bc * FFc];
__device__ float g_part[8 * MNc];      // split-K partials: O/FF2 (8 x MN) == FF1 (2 x B*FF)
__device__ float g_qkvp[6 * MNc];      // QKV split-K=2 partials: slab = mat*2+split

// ---------------- embedding + positional encoding ---------------------------
__global__ __launch_bounds__(256) void embed_kernel(
    const int* __restrict__ x, const int* __restrict__ pos_p,
    const float* __restrict__ emb, float* __restrict__ h)
{
    int i = blockIdx.x * 256 + threadIdx.x;           // 0 .. B*HID-1
    int b = i >> 9;
    int c = i & 511;
    float posf = (float)(*pos_p);
    int j2 = c & ~1;                                   // 2*j
    float e = (float)j2 * (1.0f / (float)HIDc);
    float ang = posf * powf(10000.0f, -e);
    float pe = (c & 1) ? cosf(ang) : sinf(ang);
    h[i] = emb[(size_t)x[b] * HIDc + c] + pe;
}

// ---------------- 3xTF32 tensor-core GEMM body --------------------------------
// C[M,N] = A[M,K] @ W[K,N] over k in [k0, k0+kLen), fp32-class accuracy via
// hi/lo TF32 split: acc += ahi*bhi + alo*bhi + ahi*blo.
// 64x64 tile, BK=32, 256 threads (8 warps, each warp 16x32 of C).
// act: 0 none, 2 relu (applied with bias in the epilogue).
#define BMt 64
#define BNt 64
#define BKt 32
#define LDAs 40   // BK + 8  (floats)
#define LDBs 72   // BN + 8  (floats)

__device__ __forceinline__ void gemm_tc_body(
    const float* __restrict__ A, const float* __restrict__ W,
    const float* __restrict__ bias, float* __restrict__ C,
    int N, int K, int k0, int kLen, int act)
{
    // one shared slab, carved; C-tile epilogue aliases the A region
    __shared__ __align__(16) float smem[2 * BMt * LDAs + 2 * BKt * LDBs]; // 9728 floats
    float* sAhi = smem;                         // 64*40
    float* sAlo = sAhi + BMt * LDAs;
    float* sBhi = sAlo + BMt * LDAs;            // 32*72
    float* sBlo = sBhi + BKt * LDBs;

    const int tid    = threadIdx.x;
    const int warp   = tid >> 5;
    const int warp_m = warp & 3;                // 4 slices of 16 rows
    const int warp_n = warp >> 2;               // 2 slices of 32 cols
    const int row0 = blockIdx.y * BMt;
    const int col0 = blockIdx.x * BNt;

    const float* Ag = A + (size_t)row0 * K + k0;
    const float* Wg = W + (size_t)k0 * N + col0;

    wmma::fragment<wmma::accumulator, 16, 16, 8, float> acc[2];
#pragma unroll
    for (int f = 0; f < 2; f++) wmma::fill_fragment(acc[f], 0.0f);

    // global-load slots: A tile 64x32 = 512 float4, B tile 32x64 = 512 float4
    // thread handles slots tid and tid+256
    float4 aP[2], bP[2];
#pragma unroll
    for (int u = 0; u < 2; u++) {
        int s = tid + u * 256;
        int ar = s >> 3, ac4 = s & 7;
        aP[u] = *(const float4*)(Ag + (size_t)ar * K + ac4 * 4);
        int br = s >> 4, bc4 = s & 15;
        bP[u] = *(const float4*)(Wg + (size_t)br * N + bc4 * 4);
    }

    const int ntiles = kLen / BKt;
    for (int t = 0; t < ntiles; t++) {
        // commit prefetched tile to smem with hi/lo tf32 split
#pragma unroll
        for (int u = 0; u < 2; u++) {
            int s = tid + u * 256;
            int ar = s >> 3, ac = (s & 7) * 4;
            float xs[4] = {aP[u].x, aP[u].y, aP[u].z, aP[u].w};
#pragma unroll
            for (int e = 0; e < 4; e++) {
                float x  = xs[e];
                float hi = wmma::__float_to_tf32(x);
                sAhi[ar * LDAs + ac + e] = hi;
                sAlo[ar * LDAs + ac + e] = wmma::__float_to_tf32(x - hi);
            }
            int br = s >> 4, bc = (s & 15) * 4;
            float ys[4] = {bP[u].x, bP[u].y, bP[u].z, bP[u].w};
#pragma unroll
            for (int e = 0; e < 4; e++) {
                float x  = ys[e];
                float hi = wmma::__float_to_tf32(x);
                sBhi[br * LDBs + bc + e] = hi;
                sBlo[br * LDBs + bc + e] = wmma::__float_to_tf32(x - hi);
            }
        }
        __syncthreads();

        if (t + 1 < ntiles) {                      // prefetch next tile
            const float* Ag2 = Ag + (t + 1) * BKt;
            const float* Wg2 = Wg + (size_t)(t + 1) * BKt * N;
#pragma unroll
            for (int u = 0; u < 2; u++) {
                int s = tid + u * 256;
                int ar = s >> 3, ac4 = s & 7;
                aP[u] = *(const float4*)(Ag2 + (size_t)ar * K + ac4 * 4);
                int br = s >> 4, bc4 = s & 15;
                bP[u] = *(const float4*)(Wg2 + (size_t)br * N + bc4 * 4);
            }
        }

#pragma unroll
        for (int ks = 0; ks < 4; ks++) {
            wmma::fragment<wmma::matrix_a, 16, 16, 8, wmma::precision::tf32, wmma::row_major> ahi, alo;
            wmma::load_matrix_sync(ahi, &sAhi[(warp_m * 16) * LDAs + ks * 8], LDAs);
            wmma::load_matrix_sync(alo, &sAlo[(warp_m * 16) * LDAs + ks * 8], LDAs);
#pragma unroll
            for (int f = 0; f < 2; f++) {
                wmma::fragment<wmma::matrix_b, 16, 16, 8, wmma::precision::tf32, wmma::row_major> bhi, blo;
                int bcol = warp_n * 32 + f * 16;
                wmma::load_matrix_sync(bhi, &sBhi[(ks * 8) * LDBs + bcol], LDBs);
                wmma::load_matrix_sync(blo, &sBlo[(ks * 8) * LDBs + bcol], LDBs);
                wmma::mma_sync(acc[f], ahi, bhi, acc[f]);
                wmma::mma_sync(acc[f], alo, bhi, acc[f]);
                wmma::mma_sync(acc[f], ahi, blo, acc[f]);
            }
        }
        __syncthreads();
    }

    // epilogue: fragments -> smem C tile (aliases A region) -> bias/act -> gmem
    float* cT = smem;                             // 64x64, ld 64 (4096 floats)
#pragma unroll
    for (int f = 0; f < 2; f++) {
        wmma::store_matrix_sync(&cT[(warp_m * 16) * BNt + warp_n * 32 + f * 16],
                                acc[f], BNt, wmma::mem_row_major);
    }
    __syncthreads();

#pragma unroll
    for (int u = 0; u < 4; u++) {
        int s = tid + u * 256;                    // 1024 float4 slots
        int r = s >> 4, c4 = (s & 15) * 4;
        float4 vv = *(const float4*)&cT[r * BNt + c4];
        float* pv = (float*)&vv;
        if (bias) {
#pragma unroll
            for (int e = 0; e < 4; e++) pv[e] += bias[col0 + c4 + e];
        }
        if (act == 2) {
#pragma unroll
            for (int e = 0; e < 4; e++) pv[e] = fmaxf(pv[e], 0.0f);
        }
        *(float4*)&C[(size_t)(row0 + r) * N + col0 + c4] = vv;
    }
}

// Generic GEMM; grid.z = split-K count; split z writes partial slab z of C.
__global__ __launch_bounds__(256) void gemm_kernel(
    const float* __restrict__ A, const float* __restrict__ W,
    const float* __restrict__ bias, float* __restrict__ C,
    int M, int N, int K, int act)
{
    int kLen = K / gridDim.z;
    int k0   = blockIdx.z * kLen;
    C += (size_t)blockIdx.z * M * N;
    gemm_tc_body(A, W, bias, C, N, K, k0, kLen, act);
}

// QKV GEMM, split-K=2 per matrix: grid.z in 0..5, mat = z>>1, split = z&1.
// Writes raw partials (no bias/act); epilogue fused in attn_state.
__global__ __launch_bounds__(256) void gemm_qkv_kernel(
    const float* __restrict__ A,
    const float* __restrict__ Wq, const float* __restrict__ Wk,
    const float* __restrict__ Wv, float* __restrict__ qkvp)
{
    int mat   = blockIdx.z >> 1;
    int split = blockIdx.z & 1;
    const float* W = (mat == 0) ? Wq : (mat == 1) ? Wk : Wv;
    float* C = qkvp + (size_t)blockIdx.z * MNc;
    gemm_tc_body(A, W, nullptr, C, HIDc, HIDc, split * (HIDc / 2), HIDc / 2, 0);
}

// FF1 split-K=2 reduce + bias + relu:  out = relu(p0 + p1 + bias)
__global__ __launch_bounds__(256) void reduce_bias_relu_kernel(
    const float* __restrict__ p, const float* __restrict__ bias,
    float* __restrict__ out)
{
    int i4 = blockIdx.x * 256 + threadIdx.x;      // float4 index over B*FF/4
    int i  = i4 * 4;
    int c  = i & (FFc - 1);
    float4 a = *(const float4*)&p[i];
    float4 b = *(const float4*)&p[(size_t)Bc * FFc + i];
    float4 r;
    r.x = fmaxf(a.x + b.x + bias[c + 0], 0.0f);
    r.y = fmaxf(a.y + b.y + bias[c + 1], 0.0f);
    r.z = fmaxf(a.z + b.z + bias[c + 2], 0.0f);
    r.w = fmaxf(a.w + b.w + bias[c + 3], 0.0f);
    *(float4*)&out[i] = r;
}

// ---------------- fused linear-attention state update ------------------------
// One block per (b,h). Fuses: QKV split-K reduce + bias + elu(+1);
// S_out = S + k v^T, num = q . S_out, den = q.(Z+k)+eps, attn = num/den.
__global__ __launch_bounds__(256) void attn_state_kernel(
    const float* __restrict__ S_in, const float* __restrict__ Z_in,
    const float* __restrict__ qkvp,
    const float* __restrict__ bq, const float* __restrict__ bk,
    const float* __restrict__ bv,
    float* __restrict__ S_out, float* __restrict__ Z_out,
    float* __restrict__ attn)
{
    int bh = blockIdx.x;                 // 0 .. B*H-1
    int t  = threadIdx.x;                // 256 threads
    __shared__ float qs[Dc], ks[Dc], vs[Dc];
    __shared__ float red[256];
    __shared__ float s_den;

    int voff = bh * Dc;                  // == b*HID + h*D
    if (t < Dc) {
        int c = ((bh & (Hc - 1)) << 6) + t;          // column within HID
        float qq = qkvp[voff + t] + qkvp[MNc + voff + t] + bq[c];
        qq = (qq > 0.0f) ? (qq + 1.0f) : expf(qq);   // elu(x)+1
        float kk = qkvp[2 * MNc + voff + t] + qkvp[3 * MNc + voff + t] + bk[c];
        kk = (kk > 0.0f) ? (kk + 1.0f) : expf(kk);
        float vv = qkvp[4 * MNc + voff + t] + qkvp[5 * MNc + voff + t] + bv[c];
        qs[t] = qq; ks[t] = kk; vs[t] = vv;
        float zn = Z_in[voff + t] + kk;
        Z_out[voff + t] = zn;
        red[t] = qq * zn;
    }
    __syncthreads();
    if (t == 0) {
        float s = 0.0f;
#pragma unroll
        for (int i = 0; i < Dc; i++) s += red[i];
        s_den = s + EPS_ATTN;
    }
    __syncthreads();

    int m  = t & 63;
    int d0 = t >> 6;                     // 0..3
    size_t base = (size_t)bh * (Dc * Dc);
    float pnum = 0.0f;
#pragma unroll
    for (int i = 0; i < 16; i++) {
        int d = 4 * i + d0;
        size_t idx = base + (size_t)d * Dc + m;
        float s  = S_in[idx];
        float sn = fmaf(ks[d], vs[m], s);
        S_out[idx] = sn;
        pnum = fmaf(qs[d], sn, pnum);
    }
    red[t] = pnum;
    __syncthreads();
    if (t < Dc) {
        float num = red[t] + red[t + 64] + red[t + 128] + red[t + 192];
        attn[voff + t] = num / s_den;
    }
}

// ---------------- LayerNorm (fuses split-K reduce + bias + residual) ---------
__global__ __launch_bounds__(256) void ln_kernel(
    const float* __restrict__ parts, int nparts, int partStride,
    const float* __restrict__ bias, const float* __restrict__ res,
    const float* __restrict__ g, const float* __restrict__ b,
    float* __restrict__ out)
{
    int row = blockIdx.x;                // 0..B-1
    int t   = threadIdx.x;               // 256 threads, 2 elems each
    float vv[2];
#pragma unroll
    for (int r = 0; r < 2; r++) {
        int c = t + 256 * r;
        size_t idx = (size_t)row * HIDc + c;
        float x = 0.0f;
        for (int p = 0; p < nparts; p++) x += parts[(size_t)p * partStride + idx];
        if (bias) x += bias[c];
        if (res)  x += res[idx];
        vv[r] = x;
    }
    float s = vv[0] + vv[1];
    float qsum = vv[0] * vv[0] + vv[1] * vv[1];
#pragma unroll
    for (int o = 16; o > 0; o >>= 1) {
        s    += __shfl_down_sync(0xffffffffu, s, o);
        qsum += __shfl_down_sync(0xffffffffu, qsum, o);
    }
    __shared__ float ss[8], sq[8];
    __shared__ float s_mean, s_rstd;
    int warp = t >> 5, lane = t & 31;
    if (lane == 0) { ss[warp] = s; sq[warp] = qsum; }
    __syncthreads();
    if (t == 0) {
        float S = 0.0f, Q = 0.0f;
#pragma unroll
        for (int w = 0; w < 8; w++) { S += ss[w]; Q += sq[w]; }
        float mean = S * (1.0f / (float)HIDc);
        float var  = Q * (1.0f / (float)HIDc) - mean * mean;
        s_mean = mean;
        s_rstd = rsqrtf(var + EPS_LN);
    }
    __syncthreads();
#pragma unroll
    for (int r = 0; r < 2; r++) {
        int c = t + 256 * r;
        size_t idx = (size_t)row * HIDc + c;
        out[idx] = (vv[r] - s_mean) * s_rstd * g[c] + b[c];
    }
}

// ---------------- launcher ----------------------------------------------------
extern "C" void kernel_launch(void* const* d_in, const int* in_sizes, int n_in,
                              void* d_out, int out_size)
{
    (void)in_sizes; (void)n_in; (void)out_size;

    const int*   x     = (const int*)  d_in[0];
    const int*   pos   = (const int*)  d_in[1];
    const float* S     = (const float*)d_in[2];
    const float* Z     = (const float*)d_in[3];
    const float* emb   = (const float*)d_in[4];
    const float* Wq    = (const float*)d_in[5];
    const float* bq    = (const float*)d_in[6];
    const float* Wk    = (const float*)d_in[7];
    const float* bk    = (const float*)d_in[8];
    const float* Wv    = (const float*)d_in[9];
    const float* bv    = (const float*)d_in[10];
    const float* Wo    = (const float*)d_in[11];
    const float* bo    = (const float*)d_in[12];
    const float* W1    = (const float*)d_in[13];
    const float* b1    = (const float*)d_in[14];
    const float* W2    = (const float*)d_in[15];
    const float* b2    = (const float*)d_in[16];
    const float* ln1_g = (const float*)d_in[17];
    const float* ln1_b = (const float*)d_in[18];
    const float* ln2_g = (const float*)d_in[19];
    const float* ln2_b = (const float*)d_in[20];
    const float* lnf_g = (const float*)d_in[21];
    const float* lnf_b = (const float*)d_in[22];

    float* h_buf;  cudaGetSymbolAddress((void**)&h_buf,  g_h);
    float* a_buf;  cudaGetSymbolAddress((void**)&a_buf,  g_attn);
    float* ff_buf; cudaGetSymbolAddress((void**)&ff_buf, g_ff);
    float* p_buf;  cudaGetSymbolAddress((void**)&p_buf,  g_part);
    float* qkvp;   cudaGetSymbolAddress((void**)&qkvp,   g_qkvp);

    const size_t SZ = (size_t)Bc * Hc * Dc * Dc;  // 8388608 per layer
    const size_t ZZ = (size_t)Bc * Hc * Dc;       // 131072  per layer
    const size_t MN = (size_t)MNc;                // 131072

    float* out   = (float*)d_out;
    float* out_h = out;                           // [B,HID]
    float* out_S = out + MN;                      // [L,B,H,D,D]
    float* out_Z = out + MN + (size_t)Lc * SZ;    // [L,B,H,D]

    // embedding + positional encoding
    embed_kernel<<<(Bc * HIDc) / 256, 256>>>(x, pos, emb, h_buf);

    for (int l = 0; l < Lc; l++) {
        const float* Wq_l = Wq + (size_t)l * HIDc * HIDc;
        const float* Wk_l = Wk + (size_t)l * HIDc * HIDc;
        const float* Wv_l = Wv + (size_t)l * HIDc * HIDc;
        const float* Wo_l = Wo + (size_t)l * HIDc * HIDc;
        const float* W1_l = W1 + (size_t)l * HIDc * FFc;
        const float* W2_l = W2 + (size_t)l * FFc * HIDc;

        // QKV: split-K=2 per matrix -> 192 blocks, raw partials
        gemm_qkv_kernel<<<dim3(HIDc / 64, Bc / 64, 6), 256>>>(
            h_buf, Wq_l, Wk_l, Wv_l, qkvp);

        // fused QKV-reduce + bias + elu(+1) + S/Z update + attention
        attn_state_kernel<<<Bc * Hc, 256>>>(
            S + (size_t)l * SZ, Z + (size_t)l * ZZ,
            qkvp, bq + l * HIDc, bk + l * HIDc, bv + l * HIDc,
            out_S + (size_t)l * SZ, out_Z + (size_t)l * ZZ, a_buf);

        // O projection, split-K=8 into partials (256 blocks)
        gemm_kernel<<<dim3(HIDc / 64, Bc / 64, 8), 256>>>(
            a_buf, Wo_l, nullptr, p_buf, Bc, HIDc, HIDc, 0);

        // h = LN1(h + attn@Wo + bo)
        ln_kernel<<<Bc, 256>>>(p_buf, 8, (int)MN, bo + l * HIDc, h_buf,
                               ln1_g + l * HIDc, ln1_b + l * HIDc, h_buf);

        // FF1, split-K=2 into partials (256 blocks); bias+relu in reduce
        gemm_kernel<<<dim3(FFc / 64, Bc / 64, 2), 256>>>(
            h_buf, W1_l, nullptr, p_buf, Bc, FFc, HIDc, 0);
        reduce_bias_relu_kernel<<<(Bc * FFc / 4) / 256, 256>>>(
            p_buf, b1 + l * FFc, ff_buf);

        // FF2, split-K=8 into partials (256 blocks)
        gemm_kernel<<<dim3(HIDc / 64, Bc / 64, 8), 256>>>(
            ff_buf, W2_l, nullptr, p_buf, Bc, HIDc, FFc, 0);

        // h = LN2(h + ff)
        ln_kernel<<<Bc, 256>>>(p_buf, 8, (int)MN, b2 + l * HIDc, h_buf,
                               ln2_g + l * HIDc, ln2_b + l * HIDc, h_buf);
    }

    // final LayerNorm straight into d_out
    ln_kernel<<<Bc, 256>>>(h_buf, 1, 0, nullptr, nullptr, lnf_g, lnf_b, out_h);
}

// round 10
// speedup vs baseline: 1.4900x; 1.4900x over previous
#include <cuda_runtime.h>
#include <cstdint>
#include <cstddef>

// Problem constants
#define Bc   256
#define HIDc 512
#define Hc   8
#define Dc   64
#define FFc  2048
#define Lc   6

#define EPS_ATTN 1e-6f
#define EPS_LN   1e-5f

#define MNc (Bc * HIDc)   // 131072

// ---------------- scratch (device globals; no allocations allowed) ----------
__device__ float g_h[MNc];
__device__ float g_attn[MNc];
__device__ float g_ff[Bc * FFc];
__device__ float g_part[16 * MNc];     // split-K partials: O/FF2 (16 x MN) == FF1 (4 x B*FF)
__device__ float g_qkvp[12 * MNc];     // QKV split-K=4 partials: slab = mat*4+split

// ---------------- embedding + positional encoding ---------------------------
__global__ __launch_bounds__(256) void embed_kernel(
    const int* __restrict__ x, const int* __restrict__ pos_p,
    const float* __restrict__ emb, float* __restrict__ h)
{
    int i = blockIdx.x * 256 + threadIdx.x;           // 0 .. B*HID-1
    int b = i >> 9;
    int c = i & 511;
    float posf = (float)(*pos_p);
    int j2 = c & ~1;                                   // 2*j
    float e = (float)j2 * (1.0f / (float)HIDc);
    float ang = posf * powf(10000.0f, -e);
    float pe = (c & 1) ? cosf(ang) : sinf(ang);
    h[i] = emb[(size_t)x[b] * HIDc + c] + pe;
}

// ---------------- fp32 GEMM, 64x64 tile, 128 threads, 4x8 microtile ----------
// C[M,N] = A[M,K] @ W[K,N] over k in [k0, k0+kLen).
// smem ping-pong double buffering; B columns accessed as tx*4 and tx*4+32 so
// every LDS.128 phase is a 128B conflict-free run.
#define BM 64
#define BN 64
#define BK 16
#define LDA 68

__device__ __forceinline__ void gemm_body_v3(
    const float* __restrict__ A, const float* __restrict__ W,
    const float* __restrict__ bias, float* __restrict__ C,
    int N, int K, int k0, int kLen, int act)
{
    __shared__ __align__(16) float As[2][BK][LDA];
    __shared__ __align__(16) float Ws[2][BK][BN];

    const int tid = threadIdx.x;            // 128 threads
    const int tx  = tid & 7;                // 8 column groups
    const int ty  = tid >> 3;               // 16 row groups of 4
    const int row0 = blockIdx.y * BM;
    const int col0 = blockIdx.x * BN;

    const float* Ag = A + (size_t)row0 * K + k0;
    const float* Wg = W + (size_t)k0 * N + col0;

    // per-thread global-load slots (2 float4 per operand per tile)
    int ar[2], ak[2], wr[2], wc[2];
#pragma unroll
    for (int u = 0; u < 2; u++) {
        int s = tid + u * 128;
        ar[u] = s >> 2;  ak[u] = (s & 3) * 4;
        wr[u] = s >> 4;  wc[u] = (s & 15) * 4;
    }

    float4 aR[2], wR[2];
#pragma unroll
    for (int u = 0; u < 2; u++) {
        aR[u] = *(const float4*)(Ag + (size_t)ar[u] * K + ak[u]);
        wR[u] = *(const float4*)(Wg + (size_t)wr[u] * N + wc[u]);
    }
    // commit tile 0 into buffer 0
#pragma unroll
    for (int u = 0; u < 2; u++) {
        As[0][ak[u] + 0][ar[u]] = aR[u].x;
        As[0][ak[u] + 1][ar[u]] = aR[u].y;
        As[0][ak[u] + 2][ar[u]] = aR[u].z;
        As[0][ak[u] + 3][ar[u]] = aR[u].w;
        *(float4*)&Ws[0][wr[u]][wc[u]] = wR[u];
    }
    __syncthreads();

    float acc[4][8];
#pragma unroll
    for (int i = 0; i < 4; i++)
#pragma unroll
        for (int j = 0; j < 8; j++) acc[i][j] = 0.0f;

    const int ntiles = kLen / BK;
    for (int t = 0; t < ntiles; t++) {
        const int cur = t & 1, nxt = cur ^ 1;

        if (t + 1 < ntiles) {               // prefetch next tile into regs
            const float* Ag2 = Ag + (t + 1) * BK;
            const float* Wg2 = Wg + (size_t)(t + 1) * BK * N;
#pragma unroll
            for (int u = 0; u < 2; u++) {
                aR[u] = *(const float4*)(Ag2 + (size_t)ar[u] * K + ak[u]);
                wR[u] = *(const float4*)(Wg2 + (size_t)wr[u] * N + wc[u]);
            }
        }

#pragma unroll
        for (int kk = 0; kk < BK; kk++) {
            float4 a4 = *(const float4*)&As[cur][kk][ty * 4];
            float4 w0 = *(const float4*)&Ws[cur][kk][tx * 4];
            float4 w1 = *(const float4*)&Ws[cur][kk][tx * 4 + 32];
            float a[4] = {a4.x, a4.y, a4.z, a4.w};
            float w[8] = {w0.x, w0.y, w0.z, w0.w, w1.x, w1.y, w1.z, w1.w};
#pragma unroll
            for (int i = 0; i < 4; i++)
#pragma unroll
                for (int j = 0; j < 8; j++)
                    acc[i][j] = fmaf(a[i], w[j], acc[i][j]);
        }

        if (t + 1 < ntiles) {               // commit prefetched tile
#pragma unroll
            for (int u = 0; u < 2; u++) {
                As[nxt][ak[u] + 0][ar[u]] = aR[u].x;
                As[nxt][ak[u] + 1][ar[u]] = aR[u].y;
                As[nxt][ak[u] + 2][ar[u]] = aR[u].z;
                As[nxt][ak[u] + 3][ar[u]] = aR[u].w;
                *(float4*)&Ws[nxt][wr[u]][wc[u]] = wR[u];
            }
        }
        __syncthreads();
    }

    // epilogue: two float4 stores per row
#pragma unroll
    for (int i = 0; i < 4; i++) {
        int row = row0 + ty * 4 + i;
        int c0  = col0 + tx * 4;
        int c1  = c0 + 32;
        float4 r0, r1;
        float* p0 = (float*)&r0;
        float* p1 = (float*)&r1;
#pragma unroll
        for (int j = 0; j < 4; j++) {
            float v0 = acc[i][j], v1 = acc[i][j + 4];
            if (bias) { v0 += bias[c0 + j]; v1 += bias[c1 + j]; }
            if (act == 2) { v0 = fmaxf(v0, 0.0f); v1 = fmaxf(v1, 0.0f); }
            p0[j] = v0; p1[j] = v1;
        }
        *(float4*)&C[(size_t)row * N + c0] = r0;
        *(float4*)&C[(size_t)row * N + c1] = r1;
    }
}

// Generic GEMM; grid.z = split-K count; split z writes partial slab z of C.
__global__ __launch_bounds__(128) void gemm_kernel(
    const float* __restrict__ A, const float* __restrict__ W,
    const float* __restrict__ bias, float* __restrict__ C,
    int M, int N, int K, int act)
{
    int kLen = K / gridDim.z;
    int k0   = blockIdx.z * kLen;
    C += (size_t)blockIdx.z * M * N;
    gemm_body_v3(A, W, bias, C, N, K, k0, kLen, act);
}

// QKV GEMM, split-K=4 per matrix: grid.z in 0..11, mat = z>>2, split = z&3.
// Writes raw partials; epilogue (reduce+bias+elu) fused in attn_state.
__global__ __launch_bounds__(128) void gemm_qkv_kernel(
    const float* __restrict__ A,
    const float* __restrict__ Wq, const float* __restrict__ Wk,
    const float* __restrict__ Wv, float* __restrict__ qkvp)
{
    int mat   = blockIdx.z >> 2;
    int split = blockIdx.z & 3;
    const float* W = (mat == 0) ? Wq : (mat == 1) ? Wk : Wv;
    float* C = qkvp + (size_t)blockIdx.z * MNc;
    gemm_body_v3(A, W, nullptr, C, HIDc, HIDc, split * (HIDc / 4), HIDc / 4, 0);
}

// FF1 split-K=4 reduce + bias + relu:  out = relu(p0+p1+p2+p3 + bias)
__global__ __launch_bounds__(256) void reduce_bias_relu_kernel(
    const float* __restrict__ p, const float* __restrict__ bias,
    float* __restrict__ out)
{
    int i4 = blockIdx.x * 256 + threadIdx.x;      // float4 index over B*FF/4
    int i  = i4 * 4;
    int c  = i & (FFc - 1);
    const size_t STR = (size_t)Bc * FFc;
    float4 a = *(const float4*)&p[i];
    float4 b = *(const float4*)&p[STR + i];
    float4 d = *(const float4*)&p[2 * STR + i];
    float4 e = *(const float4*)&p[3 * STR + i];
    float4 r;
    r.x = fmaxf(a.x + b.x + d.x + e.x + bias[c + 0], 0.0f);
    r.y = fmaxf(a.y + b.y + d.y + e.y + bias[c + 1], 0.0f);
    r.z = fmaxf(a.z + b.z + d.z + e.z + bias[c + 2], 0.0f);
    r.w = fmaxf(a.w + b.w + d.w + e.w + bias[c + 3], 0.0f);
    *(float4*)&out[i] = r;
}

// ---------------- fused linear-attention state update ------------------------
// One block per (b,h). Fuses: QKV split-K(4) reduce + bias + elu(+1);
// S_out = S + k v^T, num = q . S_out, den = q.(Z+k)+eps, attn = num/den.
__global__ __launch_bounds__(256) void attn_state_kernel(
    const float* __restrict__ S_in, const float* __restrict__ Z_in,
    const float* __restrict__ qkvp,
    const float* __restrict__ bq, const float* __restrict__ bk,
    const float* __restrict__ bv,
    float* __restrict__ S_out, float* __restrict__ Z_out,
    float* __restrict__ attn)
{
    int bh = blockIdx.x;                 // 0 .. B*H-1
    int t  = threadIdx.x;                // 256 threads
    __shared__ float qs[Dc], ks[Dc], vs[Dc];
    __shared__ float red[256];
    __shared__ float s_den;

    int voff = bh * Dc;                  // == b*HID + h*D
    if (t < Dc) {
        int c = ((bh & (Hc - 1)) << 6) + t;          // column within HID
        float qq = bq[c], kk = bk[c], vv = bv[c];
#pragma unroll
        for (int p = 0; p < 4; p++) {
            qq += qkvp[(size_t)p * MNc + voff + t];
            kk += qkvp[(size_t)(4 + p) * MNc + voff + t];
            vv += qkvp[(size_t)(8 + p) * MNc + voff + t];
        }
        qq = (qq > 0.0f) ? (qq + 1.0f) : expf(qq);   // elu(x)+1
        kk = (kk > 0.0f) ? (kk + 1.0f) : expf(kk);
        qs[t] = qq; ks[t] = kk; vs[t] = vv;
        float zn = Z_in[voff + t] + kk;
        Z_out[voff + t] = zn;
        red[t] = qq * zn;
    }
    __syncthreads();
    if (t == 0) {
        float s = 0.0f;
#pragma unroll
        for (int i = 0; i < Dc; i++) s += red[i];
        s_den = s + EPS_ATTN;
    }
    __syncthreads();

    int m  = t & 63;
    int d0 = t >> 6;                     // 0..3
    size_t base = (size_t)bh * (Dc * Dc);
    float pnum = 0.0f;
#pragma unroll
    for (int i = 0; i < 16; i++) {
        int d = 4 * i + d0;
        size_t idx = base + (size_t)d * Dc + m;
        float s  = S_in[idx];
        float sn = fmaf(ks[d], vs[m], s);
        S_out[idx] = sn;
        pnum = fmaf(qs[d], sn, pnum);
    }
    red[t] = pnum;
    __syncthreads();
    if (t < Dc) {
        float num = red[t] + red[t + 64] + red[t + 128] + red[t + 192];
        attn[voff + t] = num / s_den;
    }
}

// ---------------- LayerNorm (fuses split-K reduce + bias + residual) ---------
__global__ __launch_bounds__(256) void ln_kernel(
    const float* __restrict__ parts, int nparts, int partStride,
    const float* __restrict__ bias, const float* __restrict__ res,
    const float* __restrict__ g, const float* __restrict__ b,
    float* __restrict__ out)
{
    int row = blockIdx.x;                // 0..B-1
    int t   = threadIdx.x;               // 256 threads, 2 elems each
    float vv[2];
#pragma unroll
    for (int r = 0; r < 2; r++) {
        int c = t + 256 * r;
        size_t idx = (size_t)row * HIDc + c;
        float x = 0.0f;
        for (int p = 0; p < nparts; p++) x += parts[(size_t)p * partStride + idx];
        if (bias) x += bias[c];
        if (res)  x += res[idx];
        vv[r] = x;
    }
    float s = vv[0] + vv[1];
    float qsum = vv[0] * vv[0] + vv[1] * vv[1];
#pragma unroll
    for (int o = 16; o > 0; o >>= 1) {
        s    += __shfl_down_sync(0xffffffffu, s, o);
        qsum += __shfl_down_sync(0xffffffffu, qsum, o);
    }
    __shared__ float ss[8], sq[8];
    __shared__ float s_mean, s_rstd;
    int warp = t >> 5, lane = t & 31;
    if (lane == 0) { ss[warp] = s; sq[warp] = qsum; }
    __syncthreads();
    if (t == 0) {
        float S = 0.0f, Q = 0.0f;
#pragma unroll
        for (int w = 0; w < 8; w++) { S += ss[w]; Q += sq[w]; }
        float mean = S * (1.0f / (float)HIDc);
        float var  = Q * (1.0f / (float)HIDc) - mean * mean;
        s_mean = mean;
        s_rstd = rsqrtf(var + EPS_LN);
    }
    __syncthreads();
#pragma unroll
    for (int r = 0; r < 2; r++) {
        int c = t + 256 * r;
        size_t idx = (size_t)row * HIDc + c;
        out[idx] = (vv[r] - s_mean) * s_rstd * g[c] + b[c];
    }
}

// ---------------- launcher ----------------------------------------------------
extern "C" void kernel_launch(void* const* d_in, const int* in_sizes, int n_in,
                              void* d_out, int out_size)
{
    (void)in_sizes; (void)n_in; (void)out_size;

    const int*   x     = (const int*)  d_in[0];
    const int*   pos   = (const int*)  d_in[1];
    const float* S     = (const float*)d_in[2];
    const float* Z     = (const float*)d_in[3];
    const float* emb   = (const float*)d_in[4];
    const float* Wq    = (const float*)d_in[5];
    const float* bq    = (const float*)d_in[6];
    const float* Wk    = (const float*)d_in[7];
    const float* bk    = (const float*)d_in[8];
    const float* Wv    = (const float*)d_in[9];
    const float* bv    = (const float*)d_in[10];
    const float* Wo    = (const float*)d_in[11];
    const float* bo    = (const float*)d_in[12];
    const float* W1    = (const float*)d_in[13];
    const float* b1    = (const float*)d_in[14];
    const float* W2    = (const float*)d_in[15];
    const float* b2    = (const float*)d_in[16];
    const float* ln1_g = (const float*)d_in[17];
    const float* ln1_b = (const float*)d_in[18];
    const float* ln2_g = (const float*)d_in[19];
    const float* ln2_b = (const float*)d_in[20];
    const float* lnf_g = (const float*)d_in[21];
    const float* lnf_b = (const float*)d_in[22];

    float* h_buf;  cudaGetSymbolAddress((void**)&h_buf,  g_h);
    float* a_buf;  cudaGetSymbolAddress((void**)&a_buf,  g_attn);
    float* ff_buf; cudaGetSymbolAddress((void**)&ff_buf, g_ff);
    float* p_buf;  cudaGetSymbolAddress((void**)&p_buf,  g_part);
    float* qkvp;   cudaGetSymbolAddress((void**)&qkvp,   g_qkvp);

    const size_t SZ = (size_t)Bc * Hc * Dc * Dc;  // 8388608 per layer
    const size_t ZZ = (size_t)Bc * Hc * Dc;       // 131072  per layer
    const size_t MN = (size_t)MNc;                // 131072

    float* out   = (float*)d_out;
    float* out_h = out;                           // [B,HID]
    float* out_S = out + MN;                      // [L,B,H,D,D]
    float* out_Z = out + MN + (size_t)Lc * SZ;    // [L,B,H,D]

    // embedding + positional encoding
    embed_kernel<<<(Bc * HIDc) / 256, 256>>>(x, pos, emb, h_buf);

    for (int l = 0; l < Lc; l++) {
        const float* Wq_l = Wq + (size_t)l * HIDc * HIDc;
        const float* Wk_l = Wk + (size_t)l * HIDc * HIDc;
        const float* Wv_l = Wv + (size_t)l * HIDc * HIDc;
        const float* Wo_l = Wo + (size_t)l * HIDc * HIDc;
        const float* W1_l = W1 + (size_t)l * HIDc * FFc;
        const float* W2_l = W2 + (size_t)l * FFc * HIDc;

        // QKV: split-K=4 per matrix -> 384 blocks, raw partials
        gemm_qkv_kernel<<<dim3(HIDc / 64, Bc / 64, 12), 128>>>(
            h_buf, Wq_l, Wk_l, Wv_l, qkvp);

        // fused QKV-reduce + bias + elu(+1) + S/Z update + attention
        attn_state_kernel<<<Bc * Hc, 256>>>(
            S + (size_t)l * SZ, Z + (size_t)l * ZZ,
            qkvp, bq + l * HIDc, bk + l * HIDc, bv + l * HIDc,
            out_S + (size_t)l * SZ, out_Z + (size_t)l * ZZ, a_buf);

        // O projection, split-K=16 into partials (512 blocks)
        gemm_kernel<<<dim3(HIDc / 64, Bc / 64, 16), 128>>>(
            a_buf, Wo_l, nullptr, p_buf, Bc, HIDc, HIDc, 0);

        // h = LN1(h + attn@Wo + bo)
        ln_kernel<<<Bc, 256>>>(p_buf, 16, (int)MN, bo + l * HIDc, h_buf,
                               ln1_g + l * HIDc, ln1_b + l * HIDc, h_buf);

        // FF1, split-K=4 into partials (512 blocks); bias+relu in reduce
        gemm_kernel<<<dim3(FFc / 64, Bc / 64, 4), 128>>>(
            h_buf, W1_l, nullptr, p_buf, Bc, FFc, HIDc, 0);
        reduce_bias_relu_kernel<<<(Bc * FFc / 4) / 256, 256>>>(
            p_buf, b1 + l * FFc, ff_buf);

        // FF2, split-K=16 into partials (512 blocks)
        gemm_kernel<<<dim3(HIDc / 64, Bc / 64, 16), 128>>>(
            ff_buf, W2_l, nullptr, p_buf, Bc, HIDc, FFc, 0);

        // h = LN2(h + ff)
        ln_kernel<<<Bc, 256>>>(p_buf, 16, (int)MN, b2 + l * HIDc, h_buf,
                               ln2_g + l * HIDc, ln2_b + l * HIDc, h_buf);
    }

    // final LayerNorm straight into d_out
    ln_kernel<<<Bc, 256>>>(h_buf, 1, 0, nullptr, nullptr, lnf_g, lnf_b, out_h);
}

// round 11
// speedup vs baseline: 1.5019x; 1.0079x over previous
#include <cuda_runtime.h>
#include <cstdint>
#include <cstddef>

// Problem constants
#define Bc   256
#define HIDc 512
#define Hc   8
#define Dc   64
#define FFc  2048
#define Lc   6

#define EPS_ATTN 1e-6f
#define EPS_LN   1e-5f

#define MNc (Bc * HIDc)   // 131072

// ---------------- scratch (device globals; no allocations allowed) ----------
__device__ float g_h[MNc];
__device__ float g_attn[MNc];
__device__ float g_ff[Bc * FFc];
__device__ float g_part[16 * MNc];     // split-K partials: O/FF2 (16 x MN) == FF1 (4 x B*FF)
__device__ float g_qkvp[12 * MNc];     // QKV split-K=4 partials: slab = mat*4+split

// ---------------- embedding + positional encoding ---------------------------
__global__ __launch_bounds__(256) void embed_kernel(
    const int* __restrict__ x, const int* __restrict__ pos_p,
    const float* __restrict__ emb, float* __restrict__ h)
{
    int i = blockIdx.x * 256 + threadIdx.x;           // 0 .. B*HID-1
    int b = i >> 9;
    int c = i & 511;
    float posf = (float)(*pos_p);
    int j2 = c & ~1;                                   // 2*j
    float e = (float)j2 * (1.0f / (float)HIDc);
    float ang = posf * powf(10000.0f, -e);
    float pe = (c & 1) ? cosf(ang) : sinf(ang);
    h[i] = emb[(size_t)x[b] * HIDc + c] + pe;
}

// ---------------- fp32 GEMM, 64x64 tile, 128 threads, 4x8 microtile ----------
// C[M,N] = A[M,K] @ W[K,N] over k in [k0, k0+kLen).
// smem ping-pong double buffering; B columns accessed as tx*4 and tx*4+32 so
// every LDS.128 phase is a 128B conflict-free run.
#define BM 64
#define BN 64
#define BK 16
#define LDA 68

__device__ __forceinline__ void gemm_body_v3(
    const float* __restrict__ A, const float* __restrict__ W,
    const float* __restrict__ bias, float* __restrict__ C,
    int N, int K, int k0, int kLen, int act)
{
    __shared__ __align__(16) float As[2][BK][LDA];
    __shared__ __align__(16) float Ws[2][BK][BN];

    const int tid = threadIdx.x;            // 128 threads
    const int tx  = tid & 7;                // 8 column groups
    const int ty  = tid >> 3;               // 16 row groups of 4
    const int row0 = blockIdx.y * BM;
    const int col0 = blockIdx.x * BN;

    const float* Ag = A + (size_t)row0 * K + k0;
    const float* Wg = W + (size_t)k0 * N + col0;

    // per-thread global-load slots (2 float4 per operand per tile)
    int ar[2], ak[2], wr[2], wc[2];
#pragma unroll
    for (int u = 0; u < 2; u++) {
        int s = tid + u * 128;
        ar[u] = s >> 2;  ak[u] = (s & 3) * 4;
        wr[u] = s >> 4;  wc[u] = (s & 15) * 4;
    }

    float4 aR[2], wR[2];
#pragma unroll
    for (int u = 0; u < 2; u++) {
        aR[u] = *(const float4*)(Ag + (size_t)ar[u] * K + ak[u]);
        wR[u] = *(const float4*)(Wg + (size_t)wr[u] * N + wc[u]);
    }
    // commit tile 0 into buffer 0
#pragma unroll
    for (int u = 0; u < 2; u++) {
        As[0][ak[u] + 0][ar[u]] = aR[u].x;
        As[0][ak[u] + 1][ar[u]] = aR[u].y;
        As[0][ak[u] + 2][ar[u]] = aR[u].z;
        As[0][ak[u] + 3][ar[u]] = aR[u].w;
        *(float4*)&Ws[0][wr[u]][wc[u]] = wR[u];
    }
    __syncthreads();

    float acc[4][8];
#pragma unroll
    for (int i = 0; i < 4; i++)
#pragma unroll
        for (int j = 0; j < 8; j++) acc[i][j] = 0.0f;

    const int ntiles = kLen / BK;
    for (int t = 0; t < ntiles; t++) {
        const int cur = t & 1, nxt = cur ^ 1;

        if (t + 1 < ntiles) {               // prefetch next tile into regs
            const float* Ag2 = Ag + (t + 1) * BK;
            const float* Wg2 = Wg + (size_t)(t + 1) * BK * N;
#pragma unroll
            for (int u = 0; u < 2; u++) {
                aR[u] = *(const float4*)(Ag2 + (size_t)ar[u] * K + ak[u]);
                wR[u] = *(const float4*)(Wg2 + (size_t)wr[u] * N + wc[u]);
            }
        }

#pragma unroll
        for (int kk = 0; kk < BK; kk++) {
            float4 a4 = *(const float4*)&As[cur][kk][ty * 4];
            float4 w0 = *(const float4*)&Ws[cur][kk][tx * 4];
            float4 w1 = *(const float4*)&Ws[cur][kk][tx * 4 + 32];
            float a[4] = {a4.x, a4.y, a4.z, a4.w};
            float w[8] = {w0.x, w0.y, w0.z, w0.w, w1.x, w1.y, w1.z, w1.w};
#pragma unroll
            for (int i = 0; i < 4; i++)
#pragma unroll
                for (int j = 0; j < 8; j++)
                    acc[i][j] = fmaf(a[i], w[j], acc[i][j]);
        }

        if (t + 1 < ntiles) {               // commit prefetched tile
#pragma unroll
            for (int u = 0; u < 2; u++) {
                As[nxt][ak[u] + 0][ar[u]] = aR[u].x;
                As[nxt][ak[u] + 1][ar[u]] = aR[u].y;
                As[nxt][ak[u] + 2][ar[u]] = aR[u].z;
                As[nxt][ak[u] + 3][ar[u]] = aR[u].w;
                *(float4*)&Ws[nxt][wr[u]][wc[u]] = wR[u];
            }
        }
        __syncthreads();
    }

    // epilogue: two float4 stores per row
#pragma unroll
    for (int i = 0; i < 4; i++) {
        int row = row0 + ty * 4 + i;
        int c0  = col0 + tx * 4;
        int c1  = c0 + 32;
        float4 r0, r1;
        float* p0 = (float*)&r0;
        float* p1 = (float*)&r1;
#pragma unroll
        for (int j = 0; j < 4; j++) {
            float v0 = acc[i][j], v1 = acc[i][j + 4];
            if (bias) { v0 += bias[c0 + j]; v1 += bias[c1 + j]; }
            if (act == 2) { v0 = fmaxf(v0, 0.0f); v1 = fmaxf(v1, 0.0f); }
            p0[j] = v0; p1[j] = v1;
        }
        *(float4*)&C[(size_t)row * N + c0] = r0;
        *(float4*)&C[(size_t)row * N + c1] = r1;
    }
}

// Generic GEMM; grid.z = split-K count; split z writes partial slab z of C.
__global__ __launch_bounds__(128) void gemm_kernel(
    const float* __restrict__ A, const float* __restrict__ W,
    const float* __restrict__ bias, float* __restrict__ C,
    int M, int N, int K, int act)
{
    int kLen = K / gridDim.z;
    int k0   = blockIdx.z * kLen;
    C += (size_t)blockIdx.z * M * N;
    gemm_body_v3(A, W, bias, C, N, K, k0, kLen, act);
}

// QKV GEMM, split-K=4 per matrix: grid.z in 0..11, mat = z>>2, split = z&3.
// Writes raw partials; epilogue (reduce+bias+elu) fused in attn_state.
__global__ __launch_bounds__(128) void gemm_qkv_kernel(
    const float* __restrict__ A,
    const float* __restrict__ Wq, const float* __restrict__ Wk,
    const float* __restrict__ Wv, float* __restrict__ qkvp)
{
    int mat   = blockIdx.z >> 2;
    int split = blockIdx.z & 3;
    const float* W = (mat == 0) ? Wq : (mat == 1) ? Wk : Wv;
    float* C = qkvp + (size_t)blockIdx.z * MNc;
    gemm_body_v3(A, W, nullptr, C, HIDc, HIDc, split * (HIDc / 4), HIDc / 4, 0);
}

// FF1 split-K=4 reduce + bias + relu:  out = relu(p0+p1+p2+p3 + bias)
__global__ __launch_bounds__(256) void reduce_bias_relu_kernel(
    const float* __restrict__ p, const float* __restrict__ bias,
    float* __restrict__ out)
{
    int i4 = blockIdx.x * 256 + threadIdx.x;      // float4 index over B*FF/4
    int i  = i4 * 4;
    int c  = i & (FFc - 1);
    const size_t STR = (size_t)Bc * FFc;
    float4 a = *(const float4*)&p[i];
    float4 b = *(const float4*)&p[STR + i];
    float4 d = *(const float4*)&p[2 * STR + i];
    float4 e = *(const float4*)&p[3 * STR + i];
    float4 r;
    r.x = fmaxf(a.x + b.x + d.x + e.x + bias[c + 0], 0.0f);
    r.y = fmaxf(a.y + b.y + d.y + e.y + bias[c + 1], 0.0f);
    r.z = fmaxf(a.z + b.z + d.z + e.z + bias[c + 2], 0.0f);
    r.w = fmaxf(a.w + b.w + d.w + e.w + bias[c + 3], 0.0f);
    *(float4*)&out[i] = r;
}

// ---------------- fused linear-attention state update ------------------------
// One block per (b,h). Fuses: QKV split-K(4) reduce + bias + elu(+1);
// S_out = S + k v^T, num = q . S_out, den = q.(Z+k)+eps, attn = num/den.
__global__ __launch_bounds__(256) void attn_state_kernel(
    const float* __restrict__ S_in, const float* __restrict__ Z_in,
    const float* __restrict__ qkvp,
    const float* __restrict__ bq, const float* __restrict__ bk,
    const float* __restrict__ bv,
    float* __restrict__ S_out, float* __restrict__ Z_out,
    float* __restrict__ attn)
{
    int bh = blockIdx.x;                 // 0 .. B*H-1
    int t  = threadIdx.x;                // 256 threads
    __shared__ float qs[Dc], ks[Dc], vs[Dc];
    __shared__ float red[256];
    __shared__ float s_den;

    int voff = bh * Dc;                  // == b*HID + h*D
    if (t < Dc) {
        int c = ((bh & (Hc - 1)) << 6) + t;          // column within HID
        float qq = bq[c], kk = bk[c], vv = bv[c];
#pragma unroll
        for (int p = 0; p < 4; p++) {
            qq += qkvp[(size_t)p * MNc + voff + t];
            kk += qkvp[(size_t)(4 + p) * MNc + voff + t];
            vv += qkvp[(size_t)(8 + p) * MNc + voff + t];
        }
        qq = (qq > 0.0f) ? (qq + 1.0f) : expf(qq);   // elu(x)+1
        kk = (kk > 0.0f) ? (kk + 1.0f) : expf(kk);
        qs[t] = qq; ks[t] = kk; vs[t] = vv;
        float zn = Z_in[voff + t] + kk;
        Z_out[voff + t] = zn;
        red[t] = qq * zn;
    }
    __syncthreads();
    if (t == 0) {
        float s = 0.0f;
#pragma unroll
        for (int i = 0; i < Dc; i++) s += red[i];
        s_den = s + EPS_ATTN;
    }
    __syncthreads();

    int m  = t & 63;
    int d0 = t >> 6;                     // 0..3
    size_t base = (size_t)bh * (Dc * Dc);
    float pnum = 0.0f;
#pragma unroll
    for (int i = 0; i < 16; i++) {
        int d = 4 * i + d0;
        size_t idx = base + (size_t)d * Dc + m;
        float s  = S_in[idx];
        float sn = fmaf(ks[d], vs[m], s);
        S_out[idx] = sn;
        pnum = fmaf(qs[d], sn, pnum);
    }
    red[t] = pnum;
    __syncthreads();
    if (t < Dc) {
        float num = red[t] + red[t + 64] + red[t + 128] + red[t + 192];
        attn[voff + t] = num / s_den;
    }
}

// ---------------- LayerNorm (fuses split-K reduce + bias + residual) ---------
__global__ __launch_bounds__(256) void ln_kernel(
    const float* __restrict__ parts, int nparts, int partStride,
    const float* __restrict__ bias, const float* __restrict__ res,
    const float* __restrict__ g, const float* __restrict__ b,
    float* __restrict__ out)
{
    int row = blockIdx.x;                // 0..B-1
    int t   = threadIdx.x;               // 256 threads, 2 elems each
    float vv[2];
#pragma unroll
    for (int r = 0; r < 2; r++) {
        int c = t + 256 * r;
        size_t idx = (size_t)row * HIDc + c;
        float x = 0.0f;
        for (int p = 0; p < nparts; p++) x += parts[(size_t)p * partStride + idx];
        if (bias) x += bias[c];
        if (res)  x += res[idx];
        vv[r] = x;
    }
    float s = vv[0] + vv[1];
    float qsum = vv[0] * vv[0] + vv[1] * vv[1];
#pragma unroll
    for (int o = 16; o > 0; o >>= 1) {
        s    += __shfl_down_sync(0xffffffffu, s, o);
        qsum += __shfl_down_sync(0xffffffffu, qsum, o);
    }
    __shared__ float ss[8], sq[8];
    __shared__ float s_mean, s_rstd;
    int warp = t >> 5, lane = t & 31;
    if (lane == 0) { ss[warp] = s; sq[warp] = qsum; }
    __syncthreads();
    if (t == 0) {
        float S = 0.0f, Q = 0.0f;
#pragma unroll
        for (int w = 0; w < 8; w++) { S += ss[w]; Q += sq[w]; }
        float mean = S * (1.0f / (float)HIDc);
        float var  = Q * (1.0f / (float)HIDc) - mean * mean;
        s_mean = mean;
        s_rstd = rsqrtf(var + EPS_LN);
    }
    __syncthreads();
#pragma unroll
    for (int r = 0; r < 2; r++) {
        int c = t + 256 * r;
        size_t idx = (size_t)row * HIDc + c;
        out[idx] = (vv[r] - s_mean) * s_rstd * g[c] + b[c];
    }
}

// ---------------- launcher ----------------------------------------------------
extern "C" void kernel_launch(void* const* d_in, const int* in_sizes, int n_in,
                              void* d_out, int out_size)
{
    (void)in_sizes; (void)n_in; (void)out_size;

    const int*   x     = (const int*)  d_in[0];
    const int*   pos   = (const int*)  d_in[1];
    const float* S     = (const float*)d_in[2];
    const float* Z     = (const float*)d_in[3];
    const float* emb   = (const float*)d_in[4];
    const float* Wq    = (const float*)d_in[5];
    const float* bq    = (const float*)d_in[6];
    const float* Wk    = (const float*)d_in[7];
    const float* bk    = (const float*)d_in[8];
    const float* Wv    = (const float*)d_in[9];
    const float* bv    = (const float*)d_in[10];
    const float* Wo    = (const float*)d_in[11];
    const float* bo    = (const float*)d_in[12];
    const float* W1    = (const float*)d_in[13];
    const float* b1    = (const float*)d_in[14];
    const float* W2    = (const float*)d_in[15];
    const float* b2    = (const float*)d_in[16];
    const float* ln1_g = (const float*)d_in[17];
    const float* ln1_b = (const float*)d_in[18];
    const float* ln2_g = (const float*)d_in[19];
    const float* ln2_b = (const float*)d_in[20];
    const float* lnf_g = (const float*)d_in[21];
    const float* lnf_b = (const float*)d_in[22];

    float* h_buf;  cudaGetSymbolAddress((void**)&h_buf,  g_h);
    float* a_buf;  cudaGetSymbolAddress((void**)&a_buf,  g_attn);
    float* ff_buf; cudaGetSymbolAddress((void**)&ff_buf, g_ff);
    float* p_buf;  cudaGetSymbolAddress((void**)&p_buf,  g_part);
    float* qkvp;   cudaGetSymbolAddress((void**)&qkvp,   g_qkvp);

    const size_t SZ = (size_t)Bc * Hc * Dc * Dc;  // 8388608 per layer
    const size_t ZZ = (size_t)Bc * Hc * Dc;       // 131072  per layer
    const size_t MN = (size_t)MNc;                // 131072

    float* out   = (float*)d_out;
    float* out_h = out;                           // [B,HID]
    float* out_S = out + MN;                      // [L,B,H,D,D]
    float* out_Z = out + MN + (size_t)Lc * SZ;    // [L,B,H,D]

    // embedding + positional encoding
    embed_kernel<<<(Bc * HIDc) / 256, 256>>>(x, pos, emb, h_buf);

    for (int l = 0; l < Lc; l++) {
        const float* Wq_l = Wq + (size_t)l * HIDc * HIDc;
        const float* Wk_l = Wk + (size_t)l * HIDc * HIDc;
        const float* Wv_l = Wv + (size_t)l * HIDc * HIDc;
        const float* Wo_l = Wo + (size_t)l * HIDc * HIDc;
        const float* W1_l = W1 + (size_t)l * HIDc * FFc;
        const float* W2_l = W2 + (size_t)l * FFc * HIDc;

        // QKV: split-K=4 per matrix -> 384 blocks, raw partials
        gemm_qkv_kernel<<<dim3(HIDc / 64, Bc / 64, 12), 128>>>(
            h_buf, Wq_l, Wk_l, Wv_l, qkvp);

        // fused QKV-reduce + bias + elu(+1) + S/Z update + attention
        attn_state_kernel<<<Bc * Hc, 256>>>(
            S + (size_t)l * SZ, Z + (size_t)l * ZZ,
            qkvp, bq + l * HIDc, bk + l * HIDc, bv + l * HIDc,
            out_S + (size_t)l * SZ, out_Z + (size_t)l * ZZ, a_buf);

        // O projection, split-K=16 into partials (512 blocks)
        gemm_kernel<<<dim3(HIDc / 64, Bc / 64, 16), 128>>>(
            a_buf, Wo_l, nullptr, p_buf, Bc, HIDc, HIDc, 0);

        // h = LN1(h + attn@Wo + bo)
        ln_kernel<<<Bc, 256>>>(p_buf, 16, (int)MN, bo + l * HIDc, h_buf,
                               ln1_g + l * HIDc, ln1_b + l * HIDc, h_buf);

        // FF1, split-K=4 into partials (512 blocks); bias+relu in reduce
        gemm_kernel<<<dim3(FFc / 64, Bc / 64, 4), 128>>>(
            h_buf, W1_l, nullptr, p_buf, Bc, FFc, HIDc, 0);
        reduce_bias_relu_kernel<<<(Bc * FFc / 4) / 256, 256>>>(
            p_buf, b1 + l * FFc, ff_buf);

        // FF2, split-K=16 into partials (512 blocks)
        gemm_kernel<<<dim3(HIDc / 64, Bc / 64, 16), 128>>>(
            ff_buf, W2_l, nullptr, p_buf, Bc, HIDc, FFc, 0);

        // h = LN2(h + ff)
        ln_kernel<<<Bc, 256>>>(p_buf, 16, (int)MN, b2 + l * HIDc, h_buf,
                               ln2_g + l * HIDc, ln2_b + l * HIDc, h_buf);
    }

    // final LayerNorm straight into d_out
    ln_kernel<<<Bc, 256>>>(h_buf, 1, 0, nullptr, nullptr, lnf_g, lnf_b, out_h);
}

// round 12
// speedup vs baseline: 1.5033x; 1.0010x over previous
#include <cuda_runtime.h>
#include <cuda_bf16.h>
#include <mma.h>
#include <cstdint>
#include <cstddef>

using namespace nvcuda;

// Problem constants
#define Bc   256
#define HIDc 512
#define Hc   8
#define Dc   64
#define FFc  2048
#define Lc   6

#define EPS_ATTN 1e-6f
#define EPS_LN   1e-5f

#define MNc (Bc * HIDc)        // 131072
#define WPL 3145728            // weight elems per layer (Wq,Wk,Wv,Wo,W1,W2)
#define WTOT (Lc * WPL)        // 18874368
// per-layer weight offsets inside the packed hi/lo arrays
#define OFF_WQ 0
#define OFF_WK 262144
#define OFF_WV 524288
#define OFF_WO 786432
#define OFF_W1 1048576
#define OFF_W2 2097152

// ---------------- scratch (device globals; no allocations allowed) ----------
__device__ float          g_h[MNc];                 // fp32 h (residual path)
__device__ __nv_bfloat16  g_hh[MNc],  g_hl[MNc];    // h hi/lo
__device__ __nv_bfloat16  g_ah[MNc],  g_al[MNc];    // attn hi/lo
__device__ __nv_bfloat16  g_fh[Bc * FFc], g_fl[Bc * FFc];  // ff hi/lo
__device__ float          g_part[8 * MNc];          // split-K partials (O/FF1/FF2)
__device__ float          g_qkvp[6 * MNc];          // QKV partials: slab = mat*2+split
__device__ __nv_bfloat16  g_whi[WTOT], g_wlo[WTOT]; // packed bf16 hi/lo weights

// ---------------- weight hi/lo split (runs once per call) -------------------
__global__ __launch_bounds__(256) void split_weights_kernel(
    const float* __restrict__ Wq, const float* __restrict__ Wk,
    const float* __restrict__ Wv, const float* __restrict__ Wo,
    const float* __restrict__ W1, const float* __restrict__ W2,
    __nv_bfloat16* __restrict__ hi, __nv_bfloat16* __restrict__ lo)
{
    size_t i = ((size_t)blockIdx.x * 256 + threadIdx.x) * 4;
    if (i >= WTOT) return;
    int l = (int)(i / WPL);
    size_t r = i - (size_t)l * WPL;
    const float* src;
    if      (r < 262144)  src = Wq + (size_t)l * 262144  + r;
    else if (r < 524288)  src = Wk + (size_t)l * 262144  + (r - 262144);
    else if (r < 786432)  src = Wv + (size_t)l * 262144  + (r - 524288);
    else if (r < 1048576) src = Wo + (size_t)l * 262144  + (r - 786432);
    else if (r < 2097152) src = W1 + (size_t)l * 1048576 + (r - 1048576);
    else                  src = W2 + (size_t)l * 1048576 + (r - 2097152);
    float4 v = *(const float4*)src;
    float xs[4] = {v.x, v.y, v.z, v.w};
#pragma unroll
    for (int e = 0; e < 4; e++) {
        __nv_bfloat16 h = __float2bfloat16(xs[e]);
        hi[i + e] = h;
        lo[i + e] = __float2bfloat16(xs[e] - __bfloat162float(h));
    }
}

// ---------------- embedding + positional encoding ---------------------------
__global__ __launch_bounds__(256) void embed_kernel(
    const int* __restrict__ x, const int* __restrict__ pos_p,
    const float* __restrict__ emb, float* __restrict__ h,
    __nv_bfloat16* __restrict__ hh, __nv_bfloat16* __restrict__ hl)
{
    int i = blockIdx.x * 256 + threadIdx.x;           // 0 .. B*HID-1
    int b = i >> 9;
    int c = i & 511;
    float posf = (float)(*pos_p);
    int j2 = c & ~1;                                   // 2*j
    float e = (float)j2 * (1.0f / (float)HIDc);
    float ang = posf * powf(10000.0f, -e);
    float pe = (c & 1) ? cosf(ang) : sinf(ang);
    float v = emb[(size_t)x[b] * HIDc + c] + pe;
    h[i] = v;
    __nv_bfloat16 vh = __float2bfloat16(v);
    hh[i] = vh;
    hl[i] = __float2bfloat16(v - __bfloat162float(vh));
}

// ---------------- bf16 hi/lo tensor-core GEMM --------------------------------
// C[M,N] = A[M,K] @ W[K,N] over k in [k0, k0+kLen), fp32-class accuracy via
// 3 bf16 MMAs: ahi*bhi + alo*bhi + ahi*blo.  64x64 tile, BK=32, 128 threads
// (4 warps, each 32x32 of C), smem ping-pong + register prefetch.
#define BKb  32
#define LDAb 40
#define LDBb 72

__device__ __forceinline__ void gemm_bf16_body(
    const __nv_bfloat16* __restrict__ Ah, const __nv_bfloat16* __restrict__ Al,
    const __nv_bfloat16* __restrict__ Wh, const __nv_bfloat16* __restrict__ Wl,
    const float* __restrict__ bias, float* __restrict__ C,
    int N, int K, int k0, int kLen, int act)
{
    __shared__ __align__(16) __nv_bfloat16 sA[2][2][64][LDAb];  // [buf][hi/lo]
    __shared__ __align__(16) __nv_bfloat16 sB[2][2][BKb][LDBb];

    const int tid   = threadIdx.x;           // 128 threads
    const int warp  = tid >> 5;
    const int wm    = warp & 1;              // 2 m-slices of 32
    const int wn    = warp >> 1;             // 2 n-slices of 32
    const int row0  = blockIdx.y * 64;
    const int col0  = blockIdx.x * 64;

    const __nv_bfloat16* Agh = Ah + (size_t)row0 * K + k0;
    const __nv_bfloat16* Agl = Al + (size_t)row0 * K + k0;
    const __nv_bfloat16* Wgh = Wh + (size_t)k0 * N + col0;
    const __nv_bfloat16* Wgl = Wl + (size_t)k0 * N + col0;

    // global slots: A tile 64x32 bf16 = 256 float4; B tile 32x64 = 256 float4
    int ar[2], ac8[2], br[2], bc8[2];
#pragma unroll
    for (int u = 0; u < 2; u++) {
        int s = tid + u * 128;
        ar[u] = s >> 2;  ac8[u] = (s & 3) * 8;
        br[u] = s >> 3;  bc8[u] = (s & 7) * 8;
    }

    float4 pAh[2], pAl[2], pBh[2], pBl[2];
#pragma unroll
    for (int u = 0; u < 2; u++) {
        pAh[u] = *(const float4*)(Agh + (size_t)ar[u] * K + ac8[u]);
        pAl[u] = *(const float4*)(Agl + (size_t)ar[u] * K + ac8[u]);
        pBh[u] = *(const float4*)(Wgh + (size_t)br[u] * N + bc8[u]);
        pBl[u] = *(const float4*)(Wgl + (size_t)br[u] * N + bc8[u]);
    }
#pragma unroll
    for (int u = 0; u < 2; u++) {
        *(float4*)&sA[0][0][ar[u]][ac8[u]] = pAh[u];
        *(float4*)&sA[0][1][ar[u]][ac8[u]] = pAl[u];
        *(float4*)&sB[0][0][br[u]][bc8[u]] = pBh[u];
        *(float4*)&sB[0][1][br[u]][bc8[u]] = pBl[u];
    }
    __syncthreads();

    wmma::fragment<wmma::accumulator, 16, 16, 16, float> acc[2][2];
#pragma unroll
    for (int mi = 0; mi < 2; mi++)
#pragma unroll
        for (int ni = 0; ni < 2; ni++) wmma::fill_fragment(acc[mi][ni], 0.0f);

    const int ntiles = kLen / BKb;
    for (int t = 0; t < ntiles; t++) {
        const int cur = t & 1, nxt = cur ^ 1;

        if (t + 1 < ntiles) {                // prefetch next tile into regs
            const __nv_bfloat16* Agh2 = Agh + (t + 1) * BKb;
            const __nv_bfloat16* Agl2 = Agl + (t + 1) * BKb;
            const __nv_bfloat16* Wgh2 = Wgh + (size_t)(t + 1) * BKb * N;
            const __nv_bfloat16* Wgl2 = Wgl + (size_t)(t + 1) * BKb * N;
#pragma unroll
            for (int u = 0; u < 2; u++) {
                pAh[u] = *(const float4*)(Agh2 + (size_t)ar[u] * K + ac8[u]);
                pAl[u] = *(const float4*)(Agl2 + (size_t)ar[u] * K + ac8[u]);
                pBh[u] = *(const float4*)(Wgh2 + (size_t)br[u] * N + bc8[u]);
                pBl[u] = *(const float4*)(Wgl2 + (size_t)br[u] * N + bc8[u]);
            }
        }

#pragma unroll
        for (int ks = 0; ks < 2; ks++) {
            wmma::fragment<wmma::matrix_a, 16, 16, 16, __nv_bfloat16, wmma::row_major> a_hi[2], a_lo[2];
            wmma::fragment<wmma::matrix_b, 16, 16, 16, __nv_bfloat16, wmma::row_major> b_hi[2], b_lo[2];
#pragma unroll
            for (int mi = 0; mi < 2; mi++) {
                int mrow = wm * 32 + mi * 16;
                wmma::load_matrix_sync(a_hi[mi], &sA[cur][0][mrow][ks * 16], LDAb);
                wmma::load_matrix_sync(a_lo[mi], &sA[cur][1][mrow][ks * 16], LDAb);
            }
#pragma unroll
            for (int ni = 0; ni < 2; ni++) {
                int ncol = wn * 32 + ni * 16;
                wmma::load_matrix_sync(b_hi[ni], &sB[cur][0][ks * 16][ncol], LDBb);
                wmma::load_matrix_sync(b_lo[ni], &sB[cur][1][ks * 16][ncol], LDBb);
            }
#pragma unroll
            for (int mi = 0; mi < 2; mi++)
#pragma unroll
                for (int ni = 0; ni < 2; ni++) {
                    wmma::mma_sync(acc[mi][ni], a_hi[mi], b_hi[ni], acc[mi][ni]);
                    wmma::mma_sync(acc[mi][ni], a_lo[mi], b_hi[ni], acc[mi][ni]);
                    wmma::mma_sync(acc[mi][ni], a_hi[mi], b_lo[ni], acc[mi][ni]);
                }
        }

        if (t + 1 < ntiles) {                // commit prefetched tile
#pragma unroll
            for (int u = 0; u < 2; u++) {
                *(float4*)&sA[nxt][0][ar[u]][ac8[u]] = pAh[u];
                *(float4*)&sA[nxt][1][ar[u]][ac8[u]] = pAl[u];
                *(float4*)&sB[nxt][0][br[u]][bc8[u]] = pBh[u];
                *(float4*)&sB[nxt][1][br[u]][bc8[u]] = pBl[u];
            }
        }
        __syncthreads();
    }

    // epilogue: fragments -> smem C tile (aliases sA) -> bias/act -> gmem
    float* cT = (float*)&sA[0][0][0][0];     // 64x64 fp32 = 16KB <= 20KB
#pragma unroll
    for (int mi = 0; mi < 2; mi++)
#pragma unroll
        for (int ni = 0; ni < 2; ni++)
            wmma::store_matrix_sync(&cT[(wm * 32 + mi * 16) * 64 + wn * 32 + ni * 16],
                                    acc[mi][ni], 64, wmma::mem_row_major);
    __syncthreads();

#pragma unroll
    for (int u = 0; u < 8; u++) {
        int s = tid + u * 128;               // 1024 float4 slots
        int r = s >> 4, c4 = (s & 15) * 4;
        float4 vv = *(const float4*)&cT[r * 64 + c4];
        float* pv = (float*)&vv;
        if (bias) {
#pragma unroll
            for (int e = 0; e < 4; e++) pv[e] += bias[col0 + c4 + e];
        }
        if (act == 2) {
#pragma unroll
            for (int e = 0; e < 4; e++) pv[e] = fmaxf(pv[e], 0.0f);
        }
        *(float4*)&C[(size_t)(row0 + r) * N + col0 + c4] = vv;
    }
}

// Generic GEMM; grid.z = split-K count; split z writes partial slab z of C.
__global__ __launch_bounds__(128) void gemm_bf16_kernel(
    const __nv_bfloat16* __restrict__ Ah, const __nv_bfloat16* __restrict__ Al,
    const __nv_bfloat16* __restrict__ Wh, const __nv_bfloat16* __restrict__ Wl,
    const float* __restrict__ bias, float* __restrict__ C,
    int M, int N, int K, int act)
{
    int kLen = K / gridDim.z;
    int k0   = blockIdx.z * kLen;
    C += (size_t)blockIdx.z * M * N;
    gemm_bf16_body(Ah, Al, Wh, Wl, bias, C, N, K, k0, kLen, act);
}

// QKV GEMM, split-K=2 per matrix: grid.z in 0..5, mat = z>>1, split = z&1.
__global__ __launch_bounds__(128) void gemm_qkv_bf16_kernel(
    const __nv_bfloat16* __restrict__ Ah, const __nv_bfloat16* __restrict__ Al,
    const __nv_bfloat16* __restrict__ WLh, const __nv_bfloat16* __restrict__ WLl,
    float* __restrict__ qkvp)
{
    int mat   = blockIdx.z >> 1;
    int split = blockIdx.z & 1;
    const __nv_bfloat16* Wh = WLh + (size_t)mat * 262144;
    const __nv_bfloat16* Wl = WLl + (size_t)mat * 262144;
    float* C = qkvp + (size_t)blockIdx.z * MNc;
    gemm_bf16_body(Ah, Al, Wh, Wl, nullptr, C, HIDc, HIDc,
                   split * (HIDc / 2), HIDc / 2, 0);
}

// FF1 split-K=2 reduce + bias + relu -> ff hi/lo bf16
__global__ __launch_bounds__(256) void reduce_bias_relu_kernel(
    const float* __restrict__ p, const float* __restrict__ bias,
    __nv_bfloat16* __restrict__ oh, __nv_bfloat16* __restrict__ ol)
{
    int i4 = blockIdx.x * 256 + threadIdx.x;      // float4 index over B*FF/4
    int i  = i4 * 4;
    int c  = i & (FFc - 1);
    const size_t STR = (size_t)Bc * FFc;
    float4 a = *(const float4*)&p[i];
    float4 b = *(const float4*)&p[STR + i];
    float xs[4] = {a.x + b.x, a.y + b.y, a.z + b.z, a.w + b.w};
#pragma unroll
    for (int e = 0; e < 4; e++) {
        float v = fmaxf(xs[e] + bias[c + e], 0.0f);
        __nv_bfloat16 vh = __float2bfloat16(v);
        oh[i + e] = vh;
        ol[i + e] = __float2bfloat16(v - __bfloat162float(vh));
    }
}

// ---------------- fused linear-attention state update ------------------------
// One block per (b,h). Fuses: QKV split-K(2) reduce + bias + elu(+1);
// S_out = S + k v^T, num = q . S_out, den = q.(Z+k)+eps, attn = num/den (hi/lo).
__global__ __launch_bounds__(256) void attn_state_kernel(
    const float* __restrict__ S_in, const float* __restrict__ Z_in,
    const float* __restrict__ qkvp,
    const float* __restrict__ bq, const float* __restrict__ bk,
    const float* __restrict__ bv,
    float* __restrict__ S_out, float* __restrict__ Z_out,
    __nv_bfloat16* __restrict__ ah, __nv_bfloat16* __restrict__ al)
{
    int bh = blockIdx.x;                 // 0 .. B*H-1
    int t  = threadIdx.x;                // 256 threads
    __shared__ float qs[Dc], ks[Dc], vs[Dc];
    __shared__ float red[256];
    __shared__ float s_den;

    int voff = bh * Dc;                  // == b*HID + h*D
    if (t < Dc) {
        int c = ((bh & (Hc - 1)) << 6) + t;          // column within HID
        float qq = bq[c] + qkvp[voff + t]              + qkvp[MNc + voff + t];
        float kk = bk[c] + qkvp[2 * (size_t)MNc + voff + t] + qkvp[3 * (size_t)MNc + voff + t];
        float vv = bv[c] + qkvp[4 * (size_t)MNc + voff + t] + qkvp[5 * (size_t)MNc + voff + t];
        qq = (qq > 0.0f) ? (qq + 1.0f) : expf(qq);   // elu(x)+1
        kk = (kk > 0.0f) ? (kk + 1.0f) : expf(kk);
        qs[t] = qq; ks[t] = kk; vs[t] = vv;
        float zn = Z_in[voff + t] + kk;
        Z_out[voff + t] = zn;
        red[t] = qq * zn;
    }
    __syncthreads();
    if (t == 0) {
        float s = 0.0f;
#pragma unroll
        for (int i = 0; i < Dc; i++) s += red[i];
        s_den = s + EPS_ATTN;
    }
    __syncthreads();

    int m  = t & 63;
    int d0 = t >> 6;                     // 0..3
    size_t base = (size_t)bh * (Dc * Dc);
    float pnum = 0.0f;
#pragma unroll
    for (int i = 0; i < 16; i++) {
        int d = 4 * i + d0;
        size_t idx = base + (size_t)d * Dc + m;
        float s  = S_in[idx];
        float sn = fmaf(ks[d], vs[m], s);
        S_out[idx] = sn;
        pnum = fmaf(qs[d], sn, pnum);
    }
    red[t] = pnum;
    __syncthreads();
    if (t < Dc) {
        float num = red[t] + red[t + 64] + red[t + 128] + red[t + 192];
        float av = num / s_den;
        __nv_bfloat16 vh = __float2bfloat16(av);
        ah[voff + t] = vh;
        al[voff + t] = __float2bfloat16(av - __bfloat162float(vh));
    }
}

// ---------------- LayerNorm (fuses split-K reduce + bias + residual) ---------
// Optionally also emits bf16 hi/lo of the output.
__global__ __launch_bounds__(256) void ln_kernel(
    const float* __restrict__ parts, int nparts, int partStride,
    const float* __restrict__ bias, const float* __restrict__ res,
    const float* __restrict__ g, const float* __restrict__ b,
    float* __restrict__ out,
    __nv_bfloat16* __restrict__ oh, __nv_bfloat16* __restrict__ ol)
{
    int row = blockIdx.x;                // 0..B-1
    int t   = threadIdx.x;               // 256 threads, 2 elems each
    float vv[2];
#pragma unroll
    for (int r = 0; r < 2; r++) {
        int c = t + 256 * r;
        size_t idx = (size_t)row * HIDc + c;
        float x = 0.0f;
        for (int p = 0; p < nparts; p++) x += parts[(size_t)p * partStride + idx];
        if (bias) x += bias[c];
        if (res)  x += res[idx];
        vv[r] = x;
    }
    float s = vv[0] + vv[1];
    float qsum = vv[0] * vv[0] + vv[1] * vv[1];
#pragma unroll
    for (int o = 16; o > 0; o >>= 1) {
        s    += __shfl_down_sync(0xffffffffu, s, o);
        qsum += __shfl_down_sync(0xffffffffu, qsum, o);
    }
    __shared__ float ss[8], sq[8];
    __shared__ float s_mean, s_rstd;
    int warp = t >> 5, lane = t & 31;
    if (lane == 0) { ss[warp] = s; sq[warp] = qsum; }
    __syncthreads();
    if (t == 0) {
        float S = 0.0f, Q = 0.0f;
#pragma unroll
        for (int w = 0; w < 8; w++) { S += ss[w]; Q += sq[w]; }
        float mean = S * (1.0f / (float)HIDc);
        float var  = Q * (1.0f / (float)HIDc) - mean * mean;
        s_mean = mean;
        s_rstd = rsqrtf(var + EPS_LN);
    }
    __syncthreads();
#pragma unroll
    for (int r = 0; r < 2; r++) {
        int c = t + 256 * r;
        size_t idx = (size_t)row * HIDc + c;
        float y = (vv[r] - s_mean) * s_rstd * g[c] + b[c];
        out[idx] = y;
        if (oh) {
            __nv_bfloat16 vh = __float2bfloat16(y);
            oh[idx] = vh;
            ol[idx] = __float2bfloat16(y - __bfloat162float(vh));
        }
    }
}

// ---------------- launcher ----------------------------------------------------
extern "C" void kernel_launch(void* const* d_in, const int* in_sizes, int n_in,
                              void* d_out, int out_size)
{
    (void)in_sizes; (void)n_in; (void)out_size;

    const int*   x     = (const int*)  d_in[0];
    const int*   pos   = (const int*)  d_in[1];
    const float* S     = (const float*)d_in[2];
    const float* Z     = (const float*)d_in[3];
    const float* emb   = (const float*)d_in[4];
    const float* Wq    = (const float*)d_in[5];
    const float* bq    = (const float*)d_in[6];
    const float* Wk    = (const float*)d_in[7];
    const float* bk    = (const float*)d_in[8];
    const float* Wv    = (const float*)d_in[9];
    const float* bv    = (const float*)d_in[10];
    const float* Wo    = (const float*)d_in[11];
    const float* bo    = (const float*)d_in[12];
    const float* W1    = (const float*)d_in[13];
    const float* b1    = (const float*)d_in[14];
    const float* W2    = (const float*)d_in[15];
    const float* b2    = (const float*)d_in[16];
    const float* ln1_g = (const float*)d_in[17];
    const float* ln1_b = (const float*)d_in[18];
    const float* ln2_g = (const float*)d_in[19];
    const float* ln2_b = (const float*)d_in[20];
    const float* lnf_g = (const float*)d_in[21];
    const float* lnf_b = (const float*)d_in[22];

    float* h_buf;          cudaGetSymbolAddress((void**)&h_buf,  g_h);
    __nv_bfloat16* hh;     cudaGetSymbolAddress((void**)&hh,     g_hh);
    __nv_bfloat16* hl;     cudaGetSymbolAddress((void**)&hl,     g_hl);
    __nv_bfloat16* ahp;    cudaGetSymbolAddress((void**)&ahp,    g_ah);
    __nv_bfloat16* alp;    cudaGetSymbolAddress((void**)&alp,    g_al);
    __nv_bfloat16* fh;     cudaGetSymbolAddress((void**)&fh,     g_fh);
    __nv_bfloat16* fl;     cudaGetSymbolAddress((void**)&fl,     g_fl);
    float* p_buf;          cudaGetSymbolAddress((void**)&p_buf,  g_part);
    float* qkvp;           cudaGetSymbolAddress((void**)&qkvp,   g_qkvp);
    __nv_bfloat16* whi;    cudaGetSymbolAddress((void**)&whi,    g_whi);
    __nv_bfloat16* wlo;    cudaGetSymbolAddress((void**)&wlo,    g_wlo);

    const size_t SZ = (size_t)Bc * Hc * Dc * Dc;  // 8388608 per layer
    const size_t ZZ = (size_t)Bc * Hc * Dc;       // 131072  per layer
    const size_t MN = (size_t)MNc;                // 131072

    float* out   = (float*)d_out;
    float* out_h = out;                           // [B,HID]
    float* out_S = out + MN;                      // [L,B,H,D,D]
    float* out_Z = out + MN + (size_t)Lc * SZ;    // [L,B,H,D]

    // weights -> bf16 hi/lo (once per call)
    split_weights_kernel<<<WTOT / 4 / 256, 256>>>(Wq, Wk, Wv, Wo, W1, W2, whi, wlo);

    // embedding + positional encoding (fp32 + hi/lo)
    embed_kernel<<<(Bc * HIDc) / 256, 256>>>(x, pos, emb, h_buf, hh, hl);

    for (int l = 0; l < Lc; l++) {
        const __nv_bfloat16* WLh = whi + (size_t)l * WPL;
        const __nv_bfloat16* WLl = wlo + (size_t)l * WPL;

        // QKV: split-K=2 per matrix -> 192 blocks, raw fp32 partials
        gemm_qkv_bf16_kernel<<<dim3(HIDc / 64, Bc / 64, 6), 128>>>(
            hh, hl, WLh, WLl, qkvp);

        // fused QKV-reduce + bias + elu(+1) + S/Z update + attention (hi/lo out)
        attn_state_kernel<<<Bc * Hc, 256>>>(
            S + (size_t)l * SZ, Z + (size_t)l * ZZ,
            qkvp, bq + l * HIDc, bk + l * HIDc, bv + l * HIDc,
            out_S + (size_t)l * SZ, out_Z + (size_t)l * ZZ, ahp, alp);

        // O projection, split-K=4 (128 blocks)
        gemm_bf16_kernel<<<dim3(HIDc / 64, Bc / 64, 4), 128>>>(
            ahp, alp, WLh + OFF_WO, WLl + OFF_WO, nullptr, p_buf,
            Bc, HIDc, HIDc, 0);

        // h = LN1(h + attn@Wo + bo)  (+ hi/lo for FF1)
        ln_kernel<<<Bc, 256>>>(p_buf, 4, (int)MN, bo + l * HIDc, h_buf,
                               ln1_g + l * HIDc, ln1_b + l * HIDc, h_buf, hh, hl);

        // FF1, split-K=2 (256 blocks); bias+relu+hi/lo in reduce
        gemm_bf16_kernel<<<dim3(FFc / 64, Bc / 64, 2), 128>>>(
            hh, hl, WLh + OFF_W1, WLl + OFF_W1, nullptr, p_buf,
            Bc, FFc, HIDc, 0);
        reduce_bias_relu_kernel<<<(Bc * FFc / 4) / 256, 256>>>(
            p_buf, b1 + l * FFc, fh, fl);

        // FF2, split-K=8 (256 blocks)
        gemm_bf16_kernel<<<dim3(HIDc / 64, Bc / 64, 8), 128>>>(
            fh, fl, WLh + OFF_W2, WLl + OFF_W2, nullptr, p_buf,
            Bc, HIDc, FFc, 0);

        // h = LN2(h + ff)  (+ hi/lo for next layer's QKV)
        ln_kernel<<<Bc, 256>>>(p_buf, 8, (int)MN, b2 + l * HIDc, h_buf,
                               ln2_g + l * HIDc, ln2_b + l * HIDc, h_buf, hh, hl);
    }

    // final LayerNorm straight into d_out
    ln_kernel<<<Bc, 256>>>(h_buf, 1, 0, nullptr, nullptr, lnf_g, lnf_b, out_h,
                           nullptr, nullptr);
}